// round 3
// baseline (speedup 1.0000x reference)
#include <cuda_runtime.h>
#include <math.h>

#define HH 2048
#define WW 2048
#define NF 64
#define MAXD 12
#define MAXLEAF 4096

struct NodeT { int idx, x0, y0, w, h; };

// Device scratch (no allocation allowed) — all state reinitialized every launch.
__device__ NodeT  g_front[2][MAXLEAF];
__device__ int    g_cnt[2];
__device__ int4   g_leafRect[MAXLEAF];       // x0, y0, w, h
__device__ float4 g_leafCol[MAXLEAF];
__device__ int    g_leafCnt;
__device__ int    g_pref[MAXLEAF + 1];       // exclusive prefix of leaf heights

// ---------------------------------------------------------------------------
// Kernel 1: build the BSP leaf list. Single block, 512 threads.
//   Phase A: per-frame argmax children (warp-parallel, first-max tie-break)
//   Phase B: level-synchronous BFS over the tree (12 levels, frontier <= 4096)
//   Phase C: block-wide exclusive scan of leaf heights -> row-job schedule
// ---------------------------------------------------------------------------
__global__ __launch_bounds__(512) void k_tree(
    const float* __restrict__ colors,
    const float* __restrict__ sel,
    const float* __restrict__ ratios)
{
    __shared__ int    s_left[NF], s_right[NF];
    __shared__ float  s_ratio[NF];
    __shared__ float4 s_col[NF];
    __shared__ int    s_sum[512];

    const int tid  = threadIdx.x;
    const int lane = tid & 31;
    const int wrp  = tid >> 5;      // 0..15

    // ---- Phase A: 128 argmax reductions (frame, side); 8 rows per warp ----
    for (int rr = 0; rr < 8; rr++) {
        int row   = wrp * 8 + rr;           // 0..127
        int frame = row >> 1;
        int side  = row & 1;
        const float* p = sel + frame * 2 * NF + side * NF;
        float v0 = p[lane], v1 = p[lane + 32];
        float v; int i;
        if (v1 > v0) { v = v1; i = lane + 32; } else { v = v0; i = lane; }
        #pragma unroll
        for (int off = 16; off >= 1; off >>= 1) {
            float ov = __shfl_xor_sync(0xffffffffu, v, off);
            int   oi = __shfl_xor_sync(0xffffffffu, i, off);
            if (ov > v || (ov == v && oi < i)) { v = ov; i = oi; }
        }
        if (lane == 0) {
            if (side == 0) s_left[frame] = i; else s_right[frame] = i;
        }
    }
    if (tid < NF) {
        s_ratio[tid] = ratios[tid];
        s_col[tid] = make_float4(colors[tid * 3], colors[tid * 3 + 1],
                                 colors[tid * 3 + 2], 0.f);
    }
    if (tid == 0) {
        g_cnt[0] = 1; g_cnt[1] = 0; g_leafCnt = 0;
        NodeT root; root.idx = 0; root.x0 = 0; root.y0 = 0; root.w = WW; root.h = HH;
        g_front[0][0] = root;
    }
    __syncthreads();

    // ---- Phase B: BFS ----
    int cur = 0;
    for (int d = 0; d < MAXD; d++) {
        int n = g_cnt[cur];
        for (int i = tid; i < n; i += 512) {
            NodeT nd = g_front[cur][i];
            if (nd.w < 2 || nd.h < 2) {                  // base case -> leaf
                int p = atomicAdd(&g_leafCnt, 1);
                g_leafRect[p] = make_int4(nd.x0, nd.y0, nd.w, nd.h);
                g_leafCol[p]  = s_col[nd.idx];
            } else {
                float rt = s_ratio[nd.idx];
                int lc = s_left[nd.idx], rc = s_right[nd.idx];
                NodeT a, b;
                if (nd.idx & 1) {                        // vertical split
                    int lw = max(1, (int)floorf((float)nd.w * rt));
                    a.idx = lc; a.x0 = nd.x0;      a.y0 = nd.y0; a.w = lw;         a.h = nd.h;
                    b.idx = rc; b.x0 = nd.x0 + lw; b.y0 = nd.y0; b.w = nd.w - lw;  b.h = nd.h;
                } else {                                 // horizontal split
                    int th = max(1, (int)floorf((float)nd.h * rt));
                    a.idx = lc; a.x0 = nd.x0; a.y0 = nd.y0;      a.w = nd.w; a.h = th;
                    b.idx = rc; b.x0 = nd.x0; b.y0 = nd.y0 + th; b.w = nd.w; b.h = nd.h - th;
                }
                int p = atomicAdd(&g_cnt[cur ^ 1], 2);
                g_front[cur ^ 1][p]     = a;
                g_front[cur ^ 1][p + 1] = b;
            }
        }
        __syncthreads();
        if (tid == 0) g_cnt[cur] = 0;
        cur ^= 1;
        __syncthreads();
    }
    // Depth-12 survivors are leaves regardless of size.
    {
        int n = g_cnt[cur];
        for (int i = tid; i < n; i += 512) {
            NodeT nd = g_front[cur][i];
            int p = atomicAdd(&g_leafCnt, 1);
            g_leafRect[p] = make_int4(nd.x0, nd.y0, nd.w, nd.h);
            g_leafCol[p]  = s_col[nd.idx];
        }
    }
    __syncthreads();

    // ---- Phase C: exclusive scan of leaf heights (L <= 4096, 8 per thread) ----
    const int L  = g_leafCnt;
    const int c0 = tid * 8;
    int hs[8];
    int chunk = 0;
    #pragma unroll
    for (int k = 0; k < 8; k++) {
        int j = c0 + k;
        hs[k] = (j < L) ? g_leafRect[j].w * 0 + ((const int*)&g_leafRect[j])[3] : 0; // .w field = height
        chunk += hs[k];
    }
    s_sum[tid] = chunk;
    __syncthreads();
    for (int off = 1; off < 512; off <<= 1) {
        int add = (tid >= off) ? s_sum[tid - off] : 0;
        __syncthreads();
        s_sum[tid] += add;
        __syncthreads();
    }
    int run = s_sum[tid] - chunk;                  // exclusive base for this chunk
    #pragma unroll
    for (int k = 0; k < 8; k++) {
        int j = c0 + k;
        if (j < L) { g_pref[j] = run; run += hs[k]; }
    }
    if (L >= c0 && L <= c0 + 8) g_pref[L] = run;   // total row-job count
}

// ---------------------------------------------------------------------------
// Kernel 2: rasterize leaves. One (leaf, row) job per warp iteration.
// ---------------------------------------------------------------------------
__global__ __launch_bounds__(256) void k_fill(float* __restrict__ out)
{
    __shared__ int s_pref[MAXLEAF + 1];

    const int L = g_leafCnt;
    const int R = g_pref[L];
    for (int i = threadIdx.x; i <= L; i += 256) s_pref[i] = g_pref[i];
    __syncthreads();

    const int lane = threadIdx.x & 31;
    const int gw   = (blockIdx.x * 256 + threadIdx.x) >> 5;
    const int nw   = (gridDim.x * 256) >> 5;

    for (int j = gw; j < R; j += nw) {
        // largest l with pref[l] <= j  (identical across lanes: smem broadcast)
        int lo = 0, hi = L - 1;
        while (lo < hi) {
            int mid = (lo + hi + 1) >> 1;
            if (s_pref[mid] <= j) lo = mid; else hi = mid - 1;
        }
        const int    r  = j - s_pref[lo];
        const int4   rc = g_leafRect[lo];
        const float4 c  = g_leafCol[lo];
        const int base = (rc.y + r) * WW + rc.x;
        const int w    = rc.z;
        for (int xi = lane; xi < w; xi += 32) {
            out[base + xi]               = c.x;
            out[HH * WW + base + xi]     = c.y;
            out[2 * HH * WW + base + xi] = c.z;
        }
    }
}

extern "C" void kernel_launch(void* const* d_in, const int* in_sizes, int n_in,
                              void* d_out, int out_size) {
    const float* colors = (const float*)d_in[0];   // frame_colors    [64, 3]
    const float* sel    = (const float*)d_in[1];   // frame_selection [64, 2, 64]
    const float* ratios = (const float*)d_in[2];   // split_ratios    [64]
    float* out = (float*)d_out;                    // [3, 2048, 2048] fp32

    k_tree<<<1, 512>>>(colors, sel, ratios);
    k_fill<<<1024, 256>>>(out);
}

// round 4
// speedup vs baseline: 3.1815x; 3.1815x over previous
#include <cuda_runtime.h>
#include <math.h>

#define HH 2048
#define WW 2048
#define NF 64
#define MAXD 12
#define NSLOT 8191            // heap-ordered tree, depths 0..12

// Explicit tree, heap order. Node j:
//   bit31=1  -> leaf; low 6 bits = frame color index
//   bit31=0  -> interior; bit30 = axis (1=vertical/x split), low 16 bits = absolute split coord
__device__ int g_tree[NSLOT + 1];

// ---------------------------------------------------------------------------
// Kernel 1: build explicit tree. 16 blocks x 512 threads; thread j walks
// root -> heap slot j independently (no atomics, no inter-block sync).
// Argmax children computed redundantly per block (cheap, warp-parallel).
// ---------------------------------------------------------------------------
__global__ __launch_bounds__(512) void k_tree(
    const float* __restrict__ sel,
    const float* __restrict__ ratios)
{
    __shared__ float s_ratio[NF];
    __shared__ int   s_left[NF], s_right[NF];

    const int tid  = threadIdx.x;
    const int lane = tid & 31;
    const int wrp  = tid >> 5;                  // 0..15

    // 128 argmax reductions (frame, side), first-max tie-break (strict >, lower idx wins)
    #pragma unroll 1
    for (int rr = 0; rr < 8; rr++) {
        int row = wrp * 8 + rr;                 // 0..127
        int frame = row >> 1, side = row & 1;
        const float* p = sel + frame * 2 * NF + side * NF;
        float v0 = p[lane], v1 = p[lane + 32];
        float v; int i;
        if (v1 > v0) { v = v1; i = lane + 32; } else { v = v0; i = lane; }
        #pragma unroll
        for (int off = 16; off >= 1; off >>= 1) {
            float ov = __shfl_xor_sync(0xffffffffu, v, off);
            int   oi = __shfl_xor_sync(0xffffffffu, i, off);
            if (ov > v || (ov == v && oi < i)) { v = ov; i = oi; }
        }
        if (lane == 0) { if (side == 0) s_left[frame] = i; else s_right[frame] = i; }
    }
    if (tid < NF) s_ratio[tid] = ratios[tid];
    __syncthreads();

    const int j = blockIdx.x * 512 + tid;
    if (j >= NSLOT) return;

    const int depth = 31 - __clz(j + 1);        // 0..12
    int idx = 0, x0 = 0, y0 = 0, w = WW, h = HH;

    // Walk the path encoded by the bits of (j+1) below its leading 1.
    for (int k = depth - 1; k >= 0; k--) {
        if (w < 2 || h < 2) return;             // an ancestor is a leaf -> slot unreachable
        int bit = ((j + 1) >> k) & 1;           // 0=left, 1=right
        float rt = s_ratio[idx];
        if (idx & 1) {                          // vertical split
            int lw = max(1, (int)floorf((float)w * rt));
            if (bit) { x0 += lw; w -= lw; idx = s_right[idx]; }
            else     { w = lw;            idx = s_left[idx];  }
        } else {                                // horizontal split
            int th = max(1, (int)floorf((float)h * rt));
            if (bit) { y0 += th; h -= th; idx = s_right[idx]; }
            else     { h = th;            idx = s_left[idx];  }
        }
    }

    if (depth == MAXD || w < 2 || h < 2) {
        g_tree[j] = (int)0x80000000 | idx;      // leaf: color index
    } else {
        float rt = s_ratio[idx];
        int v;
        if (idx & 1) v = (1 << 30) | (x0 + max(1, (int)floorf((float)w * rt)));
        else         v =             (y0 + max(1, (int)floorf((float)h * rt)));
        g_tree[j] = v;
    }
}

// ---------------------------------------------------------------------------
// Kernel 2: render. Block (32,8) = 128x8 tile, 4 px/thread.
// Thread 0 descends while the split line doesn't cross the tile; per-pixel
// descent is then just cur -> 2*cur+1+go with absolute-coordinate compares.
// hi = running min of left-turn x-splits = leaf right edge (x-run reuse).
// ---------------------------------------------------------------------------
__global__ __launch_bounds__(256) void k_render(
    const float* __restrict__ colors,
    float* __restrict__ out)
{
    __shared__ float4 s_col[NF];
    __shared__ int    s_pre[2];                 // cur, hi

    const int t = threadIdx.y * 32 + threadIdx.x;
    if (t < NF)
        s_col[t] = make_float4(colors[3 * t], colors[3 * t + 1], colors[3 * t + 2], 0.f);

    const int tx0 = blockIdx.x * 128;
    const int ty0 = blockIdx.y * 8;

    if (t == 0) {
        int cur = 0, hi = WW;
        int v = g_tree[0];
        while (v >= 0) {
            int s = v & 0xFFFF;
            if (v & (1 << 30)) {                // vertical split
                if      (tx0 + 128 <= s) { hi = min(hi, s); cur = 2 * cur + 1; }
                else if (tx0 >= s)       {                  cur = 2 * cur + 2; }
                else break;                     // crosses tile in x
            } else {                            // horizontal split
                if      (ty0 + 8 <= s)   cur = 2 * cur + 1;
                else if (ty0 >= s)       cur = 2 * cur + 2;
                else break;                     // crosses tile in y
            }
            v = g_tree[cur];
        }
        s_pre[0] = cur; s_pre[1] = hi;
    }
    __syncthreads();

    const int xbase = tx0 + threadIdx.x * 4;
    const int y     = ty0 + threadIdx.y;
    const int pcur  = s_pre[0];
    const int phi   = s_pre[1];

    float r[4], g[4], b[4];
    float4 col = make_float4(0.f, 0.f, 0.f, 0.f);
    int reachx = -1;                            // exclusive x end of current leaf

    #pragma unroll
    for (int q = 0; q < 4; q++) {
        int xq = xbase + q;
        if (xq >= reachx) {
            int cur = pcur, hi = phi;
            int v = __ldg(&g_tree[cur]);
            while (v >= 0) {
                int s = v & 0xFFFF;
                int coord = (v & (1 << 30)) ? xq : y;
                if (coord >= s) { cur = 2 * cur + 2; }
                else {
                    cur = 2 * cur + 1;
                    if (v & (1 << 30)) hi = min(hi, s);
                }
                v = __ldg(&g_tree[cur]);
            }
            col = s_col[v & 63];
            reachx = hi;
        }
        r[q] = col.x; g[q] = col.y; b[q] = col.z;
    }

    const int p = y * WW + xbase;
    *reinterpret_cast<float4*>(out + p)               = make_float4(r[0], r[1], r[2], r[3]);
    *reinterpret_cast<float4*>(out + HH * WW + p)     = make_float4(g[0], g[1], g[2], g[3]);
    *reinterpret_cast<float4*>(out + 2 * HH * WW + p) = make_float4(b[0], b[1], b[2], b[3]);
}

extern "C" void kernel_launch(void* const* d_in, const int* in_sizes, int n_in,
                              void* d_out, int out_size) {
    const float* colors = (const float*)d_in[0];   // frame_colors    [64, 3]
    const float* sel    = (const float*)d_in[1];   // frame_selection [64, 2, 64]
    const float* ratios = (const float*)d_in[2];   // split_ratios    [64]
    float* out = (float*)d_out;                    // [3, 2048, 2048] fp32

    k_tree<<<16, 512>>>(sel, ratios);

    dim3 block(32, 8);
    dim3 grid(WW / 128, HH / 8);
    k_render<<<grid, block>>>(colors, out);
}

// round 5
// speedup vs baseline: 3.5145x; 1.1047x over previous
#include <cuda_runtime.h>
#include <math.h>

#define HH 2048
#define WW 2048
#define NF 64
#define MAXD 12
#define NSLOT 8191            // heap-ordered tree, depths 0..12
#define PXW 32                // patch width  (warp x-span)
#define PXH 4                 // patch height (rows per thread)
#define NPX (WW / PXW)        // 64
#define NPY (HH / PXH)        // 512

// Explicit tree, heap order. Node j:
//   bit31=1 -> leaf; low 6 bits = frame color index
//   bit31=0 -> interior; bit30 = axis (1=vertical/x), low 16 bits = absolute split coord
__device__ int  g_tree[NSLOT];
__device__ int2 g_pre[NPX * NPY];   // per 32x4 patch: (prefix node, prefix y-reach)

// ---------------------------------------------------------------------------
// Kernel 1: build explicit tree. Thread j walks root -> heap slot j.
// Argmax children computed per-block (warp-parallel, first-max tie-break).
// ---------------------------------------------------------------------------
__global__ __launch_bounds__(512) void k_tree(
    const float* __restrict__ sel,
    const float* __restrict__ ratios)
{
    __shared__ float s_ratio[NF];
    __shared__ int   s_left[NF], s_right[NF];

    const int tid  = threadIdx.x;
    const int lane = tid & 31;
    const int wrp  = tid >> 5;                  // 0..15

    #pragma unroll 1
    for (int rr = 0; rr < 8; rr++) {
        int row = wrp * 8 + rr;                 // 0..127
        int frame = row >> 1, side = row & 1;
        const float* p = sel + frame * 2 * NF + side * NF;
        float v0 = p[lane], v1 = p[lane + 32];
        float v; int i;
        if (v1 > v0) { v = v1; i = lane + 32; } else { v = v0; i = lane; }
        #pragma unroll
        for (int off = 16; off >= 1; off >>= 1) {
            float ov = __shfl_xor_sync(0xffffffffu, v, off);
            int   oi = __shfl_xor_sync(0xffffffffu, i, off);
            if (ov > v || (ov == v && oi < i)) { v = ov; i = oi; }
        }
        if (lane == 0) { if (side == 0) s_left[frame] = i; else s_right[frame] = i; }
    }
    if (tid < NF) s_ratio[tid] = ratios[tid];
    __syncthreads();

    const int j = blockIdx.x * 512 + tid;
    if (j >= NSLOT) return;

    const int depth = 31 - __clz(j + 1);        // 0..12
    int idx = 0, x0 = 0, y0 = 0, w = WW, h = HH;

    for (int k = depth - 1; k >= 0; k--) {
        if (w < 2 || h < 2) return;             // ancestor is a leaf -> unreachable slot
        int bit = ((j + 1) >> k) & 1;
        float rt = s_ratio[idx];
        if (idx & 1) {                          // vertical split
            int lw = max(1, (int)floorf((float)w * rt));
            if (bit) { x0 += lw; w -= lw; idx = s_right[idx]; }
            else     { w = lw;            idx = s_left[idx];  }
        } else {                                // horizontal split
            int th = max(1, (int)floorf((float)h * rt));
            if (bit) { y0 += th; h -= th; idx = s_right[idx]; }
            else     { h = th;            idx = s_left[idx];  }
        }
    }

    if (depth == MAXD || w < 2 || h < 2) {
        g_tree[j] = (int)0x80000000 | idx;
    } else {
        float rt = s_ratio[idx];
        if (idx & 1) g_tree[j] = (1 << 30) | (x0 + max(1, (int)floorf((float)w * rt)));
        else         g_tree[j] =             (y0 + max(1, (int)floorf((float)h * rt)));
    }
}

// ---------------------------------------------------------------------------
// Kernel 2: per-patch prefix. Each thread descends root -> its 32x4 patch
// until the split line crosses the patch (or a leaf is reached), recording
// the running y upper bound (min of left-taken horizontal splits).
// ---------------------------------------------------------------------------
__global__ __launch_bounds__(256) void k_pre()
{
    const int id = blockIdx.x * 256 + threadIdx.x;     // 0..32767
    const int px = id & (NPX - 1);
    const int py = id >> 6;
    const int x0 = px * PXW, y0 = py * PXH;

    int cur = 0, reach = HH;
    int v = __ldg(&g_tree[0]);
    while (v >= 0) {
        int s = v & 0xFFFF;
        if (v & (1 << 30)) {                           // vertical split
            if      (x0 + PXW <= s) cur = 2 * cur + 1;
            else if (x0 >= s)       cur = 2 * cur + 2;
            else break;
        } else {                                       // horizontal split
            if      (y0 + PXH <= s) { reach = min(reach, s); cur = 2 * cur + 1; }
            else if (y0 >= s)         cur = 2 * cur + 2;
            else break;
        }
        v = __ldg(&g_tree[cur]);
    }
    g_pre[id] = make_int2(cur, reach);
}

// ---------------------------------------------------------------------------
// Kernel 3: render. Block (32,8) covers a 32x32 tile; warp = one 32x4 patch.
// Thread owns 4 rows at fixed x. y-run reuse: leaf valid while y < reachy.
// Horizontal boundaries hit many lanes at the same q -> convergent re-descents.
// ---------------------------------------------------------------------------
__global__ __launch_bounds__(256) void k_render(
    const float* __restrict__ colors,
    float* __restrict__ out)
{
    __shared__ float4 s_col[NF];
    const int t = threadIdx.y * 32 + threadIdx.x;
    if (t < NF)
        s_col[t] = make_float4(colors[3 * t], colors[3 * t + 1], colors[3 * t + 2], 0.f);
    __syncthreads();

    const int px    = blockIdx.x;                       // 0..63
    const int py    = blockIdx.y * 8 + threadIdx.y;     // 0..511
    const int x     = px * PXW + threadIdx.x;
    const int ybase = py * PXH;

    const int2 pre = __ldg(&g_pre[py * NPX + px]);

    float4 col = make_float4(0.f, 0.f, 0.f, 0.f);
    int reachy = -1;
    const int base = ybase * WW + x;

    #pragma unroll
    for (int q = 0; q < PXH; q++) {
        const int y = ybase + q;
        if (y >= reachy) {
            int cur = pre.x, ry = pre.y;
            int v = __ldg(&g_tree[cur]);
            while (v >= 0) {
                int s = v & 0xFFFF;
                bool vert = (v & (1 << 30)) != 0;
                int coord = vert ? x : y;
                if (coord >= s) cur = 2 * cur + 2;
                else { if (!vert) ry = min(ry, s); cur = 2 * cur + 1; }
                v = __ldg(&g_tree[cur]);
            }
            col = s_col[v & 63];
            reachy = ry;
        }
        out[base + q * WW]               = col.x;
        out[HH * WW + base + q * WW]     = col.y;
        out[2 * HH * WW + base + q * WW] = col.z;
    }
}

extern "C" void kernel_launch(void* const* d_in, const int* in_sizes, int n_in,
                              void* d_out, int out_size) {
    const float* colors = (const float*)d_in[0];   // frame_colors    [64, 3]
    const float* sel    = (const float*)d_in[1];   // frame_selection [64, 2, 64]
    const float* ratios = (const float*)d_in[2];   // split_ratios    [64]
    float* out = (float*)d_out;                    // [3, 2048, 2048] fp32

    k_tree<<<16, 512>>>(sel, ratios);
    k_pre<<<(NPX * NPY) / 256, 256>>>();

    dim3 block(32, 8);
    dim3 grid(NPX, NPY / 8);
    k_render<<<grid, block>>>(colors, out);
}